// round 4
// baseline (speedup 1.0000x reference)
#include <cuda_runtime.h>
#include <cuda_bf16.h>

#define MAX_NODES 100000
#define MAX_EDGES 600000
#define D 128

// Scratch (static device allocations are allowed; cudaMalloc is not).
__device__ int   g_is64;
__device__ int   g_src[MAX_EDGES];
__device__ int   g_dst[MAX_EDGES];
__device__ float g_dinv[MAX_NODES];
__device__ float g_y[(size_t)MAX_NODES * D];   // y = dinv[i] * (x[i] @ W)

// ---------------------------------------------------------------------------
// Dtype detection: int64 edge_index has zero high words (values < 1e5);
// int32 edge_index has random values at odd word positions.
// ---------------------------------------------------------------------------
__global__ void k_detect(const int* __restrict__ ei_raw) {
    int is64 = 1;
    for (int i = 1; i < 128; i += 2) {
        if (ei_raw[i] != 0) { is64 = 0; break; }
    }
    g_is64 = is64;
}

// Unpack edge list into flat int32 arrays (handles either dtype).
__global__ void k_convert(const void* __restrict__ ei, int e) {
    int i = blockIdx.x * blockDim.x + threadIdx.x;
    if (i >= e) return;
    int s, d;
    if (g_is64) {
        const long long* p = (const long long*)ei;
        s = (int)p[i];
        d = (int)p[e + i];
    } else {
        const int* p = (const int*)ei;
        s = p[i];
        d = p[e + i];
    }
    g_src[i] = s;
    g_dst[i] = d;
}

// ---------------------------------------------------------------------------
// Degree kernels
// ---------------------------------------------------------------------------
__global__ void k_deg_init(int n) {
    int i = blockIdx.x * blockDim.x + threadIdx.x;
    if (i < n) g_dinv[i] = 1.0f;  // self-loop contributes 1 to every degree
}

__global__ void k_deg(int e, int n) {
    int i = blockIdx.x * blockDim.x + threadIdx.x;
    if (i < e) {
        unsigned dst = (unsigned)g_dst[i];
        if (dst < (unsigned)n) atomicAdd(&g_dinv[dst], 1.0f);
    }
}

__global__ void k_rsqrt(int n) {
    int i = blockIdx.x * blockDim.x + threadIdx.x;
    if (i < n) g_dinv[i] = rsqrtf(g_dinv[i]);
}

// ---------------------------------------------------------------------------
// GEMM + src-side scale:  y[i,:] = dinv[i] * (x[i,:] @ W)
// Also initializes out with y (self-loop contribution before dst-side scale).
// Block: 128 threads. Tile: 16 rows x 128 cols. Thread tile: 4 rows x 4 cols.
// ---------------------------------------------------------------------------
__global__ void __launch_bounds__(128) k_gemm(const float* __restrict__ x,
                                              const float* __restrict__ W,
                                              float* __restrict__ out,
                                              int n) {
    __shared__ float Wsm[32 * 128];   // 16 KB: W[k0:k0+32, 0:128]
    __shared__ float xsm[16 * 32];    //  2 KB: x[row0:row0+16, k0:k0+32]

    const int tid = threadIdx.x;
    const int cg  = tid & 31;   // column group: cols 4*cg .. 4*cg+3
    const int rg  = tid >> 5;   // row group (warp): rows rg*4 .. rg*4+3
    const int row0 = blockIdx.x * 16;

    float acc[4][4] = {};

    for (int k0 = 0; k0 < D; k0 += 32) {
        __syncthreads();
        // Load W chunk: 32*128 = 4096 floats, 32 per thread, coalesced.
        #pragma unroll
        for (int i = 0; i < 32; i++) {
            int idx = tid + i * 128;
            Wsm[idx] = W[(size_t)(k0 + (idx >> 7)) * D + (idx & 127)];
        }
        // Load x chunk: 16*32 = 512 floats, 4 per thread.
        #pragma unroll
        for (int i = 0; i < 4; i++) {
            int idx = tid + i * 128;
            int r = idx >> 5;
            int row = row0 + r;
            if (row >= n) row = n - 1;  // clamp
            xsm[idx] = x[(size_t)row * D + k0 + (idx & 31)];
        }
        __syncthreads();

        #pragma unroll
        for (int kk4 = 0; kk4 < 8; kk4++) {
            float xs[4][4];
            #pragma unroll
            for (int r = 0; r < 4; r++) {
                float4 t = *(const float4*)&xsm[(rg * 4 + r) * 32 + kk4 * 4];
                xs[r][0] = t.x; xs[r][1] = t.y; xs[r][2] = t.z; xs[r][3] = t.w;
            }
            #pragma unroll
            for (int j = 0; j < 4; j++) {
                float4 w = *(const float4*)&Wsm[(kk4 * 4 + j) * 128 + cg * 4];
                #pragma unroll
                for (int r = 0; r < 4; r++) {
                    acc[r][0] = fmaf(xs[r][j], w.x, acc[r][0]);
                    acc[r][1] = fmaf(xs[r][j], w.y, acc[r][1]);
                    acc[r][2] = fmaf(xs[r][j], w.z, acc[r][2]);
                    acc[r][3] = fmaf(xs[r][j], w.w, acc[r][3]);
                }
            }
        }
    }

    // Epilogue: scale by dinv[row], write y and init out (= self-loop msg).
    #pragma unroll
    for (int r = 0; r < 4; r++) {
        int row = row0 + rg * 4 + r;
        if (row < n) {
            float s = g_dinv[row];
            float4 v;
            v.x = acc[r][0] * s; v.y = acc[r][1] * s;
            v.z = acc[r][2] * s; v.w = acc[r][3] * s;
            *(float4*)&g_y[(size_t)row * D + cg * 4] = v;
            *(float4*)&out[(size_t)row * D + cg * 4] = v;
        }
    }
}

// ---------------------------------------------------------------------------
// Edge scatter: one warp per edge, lane handles 4 contiguous floats.
// out[dst, :] += y[src, :]   (vector red.global.add.v4.f32)
// ---------------------------------------------------------------------------
__device__ __forceinline__ void red_add_v4(float* addr, float4 v) {
    asm volatile("red.global.add.v4.f32 [%0], {%1, %2, %3, %4};"
                 :: "l"(addr), "f"(v.x), "f"(v.y), "f"(v.z), "f"(v.w)
                 : "memory");
}

__global__ void __launch_bounds__(256) k_scatter(float* __restrict__ out,
                                                 int e, int n) {
    int warp = blockIdx.x * (blockDim.x >> 5) + (threadIdx.x >> 5);
    if (warp >= e) return;
    int lane = threadIdx.x & 31;

    unsigned src = (unsigned)g_src[warp];
    unsigned dst = (unsigned)g_dst[warp];
    if (src >= (unsigned)n || dst >= (unsigned)n) return;

    float4 v = *(const float4*)&g_y[(size_t)src * D + lane * 4];
    red_add_v4(&out[(size_t)dst * D + lane * 4], v);
}

// ---------------------------------------------------------------------------
// Finalize: out[i,:] = dinv[i] * out[i,:] + b
// ---------------------------------------------------------------------------
__global__ void k_final(const float* __restrict__ b, float* __restrict__ out,
                        int n) {
    int i = blockIdx.x * blockDim.x + threadIdx.x;  // float4 index
    if (i < n * 32) {
        float s = g_dinv[i >> 5];
        float4 v = ((const float4*)out)[i];
        float4 bb = ((const float4*)b)[i & 31];
        v.x = fmaf(v.x, s, bb.x);
        v.y = fmaf(v.y, s, bb.y);
        v.z = fmaf(v.z, s, bb.z);
        v.w = fmaf(v.w, s, bb.w);
        ((float4*)out)[i] = v;
    }
}

// ---------------------------------------------------------------------------
extern "C" void kernel_launch(void* const* d_in, const int* in_sizes, int n_in,
                              void* d_out, int out_size) {
    const float* x  = (const float*)d_in[0];
    const void*  ei = (const void*)d_in[1];
    const float* W  = (const float*)d_in[2];
    const float* b  = (const float*)d_in[3];
    float* out = (float*)d_out;

    int n = in_sizes[0] / D;   // 100000
    int e = in_sizes[1] / 2;   // 600000

    k_detect<<<1, 1>>>((const int*)ei);
    k_convert<<<(e + 255) / 256, 256>>>(ei, e);

    k_deg_init<<<(n + 255) / 256, 256>>>(n);
    k_deg<<<(e + 255) / 256, 256>>>(e, n);
    k_rsqrt<<<(n + 255) / 256, 256>>>(n);

    k_gemm<<<(n + 15) / 16, 128>>>(x, W, out, n);

    k_scatter<<<(e + 7) / 8, 256>>>(out, e, n);

    k_final<<<(n * 32 + 255) / 256, 256>>>(b, out, n);
}

// round 6
// speedup vs baseline: 1.2207x; 1.2207x over previous
#include <cuda_runtime.h>
#include <cuda_bf16.h>
#include <cstdint>

#define MAX_NODES 100000
#define MAX_EDGES 600000
#define D 128
#define TILE_M 128
#define GEMM_THREADS 256
#define LDA 136                    // padded row stride (elements) -> 272B, LDSM conflict-free

// ---------------------------------------------------------------------------
// Device scratch (no cudaMalloc allowed)
// ---------------------------------------------------------------------------
__device__ int   g_is64;
__device__ int   g_src[MAX_EDGES];
__device__ int   g_dst[MAX_EDGES];
__device__ float g_dinv[MAX_NODES];
__device__ float g_y[(size_t)MAX_NODES * D];   // y = dinv[i] * (x[i] @ W)

// ---------------------------------------------------------------------------
// PTX helpers: ldmatrix + bf16 mma.sync (no sm_103a-only features!)
// ---------------------------------------------------------------------------
__device__ __forceinline__ uint32_t smem_u32(const void* p) {
    uint32_t a;
    asm("{ .reg .u64 t; cvta.to.shared.u64 t, %1; cvt.u32.u64 %0, t; }"
        : "=r"(a) : "l"(p));
    return a;
}

__device__ __forceinline__ void ldsm_x4(uint32_t& r0, uint32_t& r1,
                                        uint32_t& r2, uint32_t& r3,
                                        uint32_t addr) {
    asm volatile("ldmatrix.sync.aligned.m8n8.x4.shared.b16 {%0,%1,%2,%3}, [%4];"
                 : "=r"(r0), "=r"(r1), "=r"(r2), "=r"(r3) : "r"(addr));
}

__device__ __forceinline__ void ldsm_x2_trans(uint32_t& r0, uint32_t& r1,
                                              uint32_t addr) {
    asm volatile("ldmatrix.sync.aligned.m8n8.x2.trans.shared.b16 {%0,%1}, [%2];"
                 : "=r"(r0), "=r"(r1) : "r"(addr));
}

__device__ __forceinline__ void mma_bf16(float* c, const uint32_t* a,
                                         const uint32_t* b) {
    asm volatile(
        "mma.sync.aligned.m16n8k16.row.col.f32.bf16.bf16.f32 "
        "{%0,%1,%2,%3}, {%4,%5,%6,%7}, {%8,%9}, {%0,%1,%2,%3};"
        : "+f"(c[0]), "+f"(c[1]), "+f"(c[2]), "+f"(c[3])
        : "r"(a[0]), "r"(a[1]), "r"(a[2]), "r"(a[3]), "r"(b[0]), "r"(b[1]));
}

// ---------------------------------------------------------------------------
// Edge dtype detection + convert + degree count (fused)
// ---------------------------------------------------------------------------
__global__ void k_detect(const int* __restrict__ ei_raw) {
    int is64 = 1;
    for (int i = 1; i < 128; i += 2)
        if (ei_raw[i] != 0) { is64 = 0; break; }
    g_is64 = is64;
}

__global__ void k_deg_init(int n) {
    int i = blockIdx.x * blockDim.x + threadIdx.x;
    if (i < n) g_dinv[i] = 1.0f;  // self-loop
}

__global__ void k_convert(const void* __restrict__ ei, int e, int n) {
    int i = blockIdx.x * blockDim.x + threadIdx.x;
    if (i >= e) return;
    int s, d;
    if (g_is64) {
        const long long* p = (const long long*)ei;
        s = (int)p[i];
        d = (int)p[e + i];
    } else {
        const int* p = (const int*)ei;
        s = p[i];
        d = p[e + i];
    }
    g_src[i] = s;
    g_dst[i] = d;
    if ((unsigned)d < (unsigned)n) atomicAdd(&g_dinv[d], 1.0f);
}

__global__ void k_rsqrt(int n) {
    int i = blockIdx.x * blockDim.x + threadIdx.x;
    if (i < n) g_dinv[i] = rsqrtf(g_dinv[i]);
}

// ---------------------------------------------------------------------------
// HMMA GEMM: y = dinv * (x @ W) via bf16 hi/lo 3-term split.
// Per CTA: M=128 rows x N=128 x K=128. 8 warps, warp w -> rows 16w..16w+15.
// A (x) stored row-major [m][k] bf16 (hi/lo planes); B = W stored [k][n]
// row-major (hi/lo), loaded with ldmatrix.trans to get col-major fragments.
// Also initializes out with y (self-loop contribution).
// ---------------------------------------------------------------------------
#define SM_A_HI 0
#define SM_A_LO (SM_A_HI + 128 * LDA * 2)   // 34816
#define SM_B_HI (SM_A_LO + 128 * LDA * 2)
#define SM_B_LO (SM_B_HI + 128 * LDA * 2)
#define SMEM_TOTAL (SM_B_LO + 128 * LDA * 2)  // 139264

__global__ void __launch_bounds__(GEMM_THREADS, 1)
k_gemm_mma(const float* __restrict__ x, const float* __restrict__ W,
           float* __restrict__ out, int n) {
    extern __shared__ __align__(16) char smem[];
    const uint32_t smem_base = smem_u32(smem);
    const int tid  = threadIdx.x;
    const int w    = tid >> 5;
    const int lane = tid & 31;
    const int row0 = blockIdx.x * TILE_M;

    // --- Convert W[k][n] -> Bs_hi/Bs_lo (row-major [k][n], padded) ---
    #pragma unroll 4
    for (int i = tid; i < 128 * 32; i += GEMM_THREADS) {   // float4 granularity
        int r  = i >> 5;
        int c4 = (i & 31) * 4;
        float4 v = *(const float4*)&W[r * D + c4];
        __nv_bfloat16 hx = __float2bfloat16(v.x), hy = __float2bfloat16(v.y);
        __nv_bfloat16 hz = __float2bfloat16(v.z), hw = __float2bfloat16(v.w);
        __nv_bfloat16 lx = __float2bfloat16(v.x - __bfloat162float(hx));
        __nv_bfloat16 ly = __float2bfloat16(v.y - __bfloat162float(hy));
        __nv_bfloat16 lz = __float2bfloat16(v.z - __bfloat162float(hz));
        __nv_bfloat16 lw = __float2bfloat16(v.w - __bfloat162float(hw));
        size_t o = (size_t)(r * LDA + c4) * 2;
        *(__nv_bfloat162*)(smem + SM_B_HI + o)     = __nv_bfloat162(hx, hy);
        *(__nv_bfloat162*)(smem + SM_B_HI + o + 4) = __nv_bfloat162(hz, hw);
        *(__nv_bfloat162*)(smem + SM_B_LO + o)     = __nv_bfloat162(lx, ly);
        *(__nv_bfloat162*)(smem + SM_B_LO + o + 4) = __nv_bfloat162(lz, lw);
    }

    // --- Convert x tile -> As_hi/As_lo (row-major [m][k], padded) ---
    #pragma unroll 4
    for (int i = tid; i < 128 * 32; i += GEMM_THREADS) {
        int r  = i >> 5;
        int c4 = (i & 31) * 4;
        int row = row0 + r;
        if (row >= n) row = n - 1;   // clamp; OOB rows never stored
        float4 v = *(const float4*)&x[(size_t)row * D + c4];
        __nv_bfloat16 hx = __float2bfloat16(v.x), hy = __float2bfloat16(v.y);
        __nv_bfloat16 hz = __float2bfloat16(v.z), hw = __float2bfloat16(v.w);
        __nv_bfloat16 lx = __float2bfloat16(v.x - __bfloat162float(hx));
        __nv_bfloat16 ly = __float2bfloat16(v.y - __bfloat162float(hy));
        __nv_bfloat16 lz = __float2bfloat16(v.z - __bfloat162float(hz));
        __nv_bfloat16 lw = __float2bfloat16(v.w - __bfloat162float(hw));
        size_t o = (size_t)(r * LDA + c4) * 2;
        *(__nv_bfloat162*)(smem + SM_A_HI + o)     = __nv_bfloat162(hx, hy);
        *(__nv_bfloat162*)(smem + SM_A_HI + o + 4) = __nv_bfloat162(hz, hw);
        *(__nv_bfloat162*)(smem + SM_A_LO + o)     = __nv_bfloat162(lx, ly);
        *(__nv_bfloat162*)(smem + SM_A_LO + o + 4) = __nv_bfloat162(lz, lw);
    }
    __syncthreads();

    // --- Mainloop: 8 k-steps (k16), 16 n-tiles (n8), 3 split terms each ---
    float acc[16][4];
    #pragma unroll
    for (int t = 0; t < 16; t++)
        acc[t][0] = acc[t][1] = acc[t][2] = acc[t][3] = 0.0f;

    const int m0 = w * 16;
    // ldmatrix A addressing: lane -> matrix (lane>>3), row-in-matrix (lane&7)
    const int amat = lane >> 3;            // 0..3
    const int arow = m0 + ((amat & 1) * 8) + (lane & 7);
    const int acol8 = (amat >> 1) * 8;     // k-offset 0 or 8
    // ldmatrix B addressing (x2): matrices 0,1 from lanes 0..15
    const int bmat = (lane >> 3) & 1;
    const int brow_base = bmat * 8 + (lane & 7);

    #pragma unroll
    for (int ks = 0; ks < 8; ks++) {
        uint32_t a_hi[4], a_lo[4];
        uint32_t a_addr = smem_base + SM_A_HI +
                          (uint32_t)(arow * LDA + ks * 16 + acol8) * 2;
        ldsm_x4(a_hi[0], a_hi[1], a_hi[2], a_hi[3], a_addr);
        ldsm_x4(a_lo[0], a_lo[1], a_lo[2], a_lo[3],
                a_addr + (SM_A_LO - SM_A_HI));

        uint32_t b_base = smem_base + SM_B_HI +
                          (uint32_t)((ks * 16 + brow_base) * LDA) * 2;
        #pragma unroll
        for (int nt = 0; nt < 16; nt++) {
            uint32_t b_hi[2], b_lo[2];
            uint32_t b_addr = b_base + nt * 16;   // n0 = nt*8, *2 bytes
            ldsm_x2_trans(b_hi[0], b_hi[1], b_addr);
            ldsm_x2_trans(b_lo[0], b_lo[1], b_addr + (SM_B_LO - SM_B_HI));
            mma_bf16(acc[nt], a_hi, b_hi);
            mma_bf16(acc[nt], a_hi, b_lo);
            mma_bf16(acc[nt], a_lo, b_hi);
        }
    }

    // --- Epilogue: scale by dinv, write y and out (self-loop) ---
    const int r_lo  = lane >> 2;          // 0..7
    const int cpair = (lane & 3) * 2;
    const int row_a = row0 + m0 + r_lo;
    const int row_b = row_a + 8;
    const float sa = (row_a < n) ? g_dinv[row_a] : 0.0f;
    const float sb = (row_b < n) ? g_dinv[row_b] : 0.0f;

    #pragma unroll
    for (int nt = 0; nt < 16; nt++) {
        int col = nt * 8 + cpair;
        if (row_a < n) {
            float2 v = make_float2(acc[nt][0] * sa, acc[nt][1] * sa);
            *(float2*)&g_y[(size_t)row_a * D + col] = v;
            *(float2*)&out[(size_t)row_a * D + col] = v;
        }
        if (row_b < n) {
            float2 v = make_float2(acc[nt][2] * sb, acc[nt][3] * sb);
            *(float2*)&g_y[(size_t)row_b * D + col] = v;
            *(float2*)&out[(size_t)row_b * D + col] = v;
        }
    }
}

// ---------------------------------------------------------------------------
// Edge scatter: one warp per edge, lane handles 4 contiguous floats.
// out[dst, :] += y[src, :]   (vector red.global.add.v4.f32)
// ---------------------------------------------------------------------------
__device__ __forceinline__ void red_add_v4(float* addr, float4 v) {
    asm volatile("red.global.add.v4.f32 [%0], {%1, %2, %3, %4};"
                 :: "l"(addr), "f"(v.x), "f"(v.y), "f"(v.z), "f"(v.w)
                 : "memory");
}

__global__ void __launch_bounds__(256) k_scatter(float* __restrict__ out,
                                                 int e, int n) {
    int warp = blockIdx.x * (blockDim.x >> 5) + (threadIdx.x >> 5);
    if (warp >= e) return;
    int lane = threadIdx.x & 31;

    unsigned src = (unsigned)g_src[warp];
    unsigned dst = (unsigned)g_dst[warp];
    if (src >= (unsigned)n || dst >= (unsigned)n) return;

    float4 v = *(const float4*)&g_y[(size_t)src * D + lane * 4];
    red_add_v4(&out[(size_t)dst * D + lane * 4], v);
}

// ---------------------------------------------------------------------------
// Finalize: out[i,:] = dinv[i] * out[i,:] + b
// ---------------------------------------------------------------------------
__global__ void k_final(const float* __restrict__ b, float* __restrict__ out,
                        int n) {
    int i = blockIdx.x * blockDim.x + threadIdx.x;  // float4 index
    if (i < n * 32) {
        float s = g_dinv[i >> 5];
        float4 v = ((const float4*)out)[i];
        float4 bb = ((const float4*)b)[i & 31];
        v.x = fmaf(v.x, s, bb.x);
        v.y = fmaf(v.y, s, bb.y);
        v.z = fmaf(v.z, s, bb.z);
        v.w = fmaf(v.w, s, bb.w);
        ((float4*)out)[i] = v;
    }
}

// ---------------------------------------------------------------------------
extern "C" void kernel_launch(void* const* d_in, const int* in_sizes, int n_in,
                              void* d_out, int out_size) {
    const float* x  = (const float*)d_in[0];
    const void*  ei = (const void*)d_in[1];
    const float* W  = (const float*)d_in[2];
    const float* b  = (const float*)d_in[3];
    float* out = (float*)d_out;

    int n = in_sizes[0] / D;   // 100000
    int e = in_sizes[1] / 2;   // 600000

    k_detect<<<1, 1>>>((const int*)ei);
    k_deg_init<<<(n + 255) / 256, 256>>>(n);
    k_convert<<<(e + 255) / 256, 256>>>(ei, e, n);
    k_rsqrt<<<(n + 255) / 256, 256>>>(n);

    cudaFuncSetAttribute(k_gemm_mma, cudaFuncAttributeMaxDynamicSharedMemorySize,
                         SMEM_TOTAL);
    k_gemm_mma<<<(n + TILE_M - 1) / TILE_M, GEMM_THREADS, SMEM_TOTAL>>>(x, W, out, n);

    k_scatter<<<(e + 7) / 8, 256>>>(out, e, n);

    k_final<<<(n * 32 + 255) / 256, 256>>>(b, out, n);
}

// round 7
// speedup vs baseline: 1.2480x; 1.0223x over previous
#include <cuda_runtime.h>
#include <cuda_bf16.h>
#include <cstdint>

#define MAX_NODES 100000
#define MAX_EDGES 600000
#define D 128
#define TILE_M 128
#define GEMM_THREADS 256
#define LDA 136                    // padded row stride (elements) -> 272B, LDSM conflict-free

// ---------------------------------------------------------------------------
// Device scratch (no cudaMalloc allowed)
// ---------------------------------------------------------------------------
__device__ int   g_is64;
__device__ int   g_src[MAX_EDGES];
__device__ int   g_dst[MAX_EDGES];
__device__ float g_deg[MAX_NODES];                 // degree incl. self-loop
__device__ float g_y[(size_t)MAX_NODES * D];       // y = dinv[i] * (x[i] @ W)
__device__ uint4 g_Whi4[2048];                     // W hi plane, bf16 [k][n]
__device__ uint4 g_Wlo4[2048];                     // W lo plane, bf16 [k][n]

// ---------------------------------------------------------------------------
// PTX helpers: ldmatrix + bf16 mma.sync (plain sm_103-safe, no tcgen05)
// ---------------------------------------------------------------------------
__device__ __forceinline__ uint32_t smem_u32(const void* p) {
    uint32_t a;
    asm("{ .reg .u64 t; cvta.to.shared.u64 t, %1; cvt.u32.u64 %0, t; }"
        : "=r"(a) : "l"(p));
    return a;
}

__device__ __forceinline__ void ldsm_x4(uint32_t& r0, uint32_t& r1,
                                        uint32_t& r2, uint32_t& r3,
                                        uint32_t addr) {
    asm volatile("ldmatrix.sync.aligned.m8n8.x4.shared.b16 {%0,%1,%2,%3}, [%4];"
                 : "=r"(r0), "=r"(r1), "=r"(r2), "=r"(r3) : "r"(addr));
}

__device__ __forceinline__ void ldsm_x2_trans(uint32_t& r0, uint32_t& r1,
                                              uint32_t addr) {
    asm volatile("ldmatrix.sync.aligned.m8n8.x2.trans.shared.b16 {%0,%1}, [%2];"
                 : "=r"(r0), "=r"(r1) : "r"(addr));
}

__device__ __forceinline__ void mma_bf16(float* c, const uint32_t* a,
                                         const uint32_t* b) {
    asm volatile(
        "mma.sync.aligned.m16n8k16.row.col.f32.bf16.bf16.f32 "
        "{%0,%1,%2,%3}, {%4,%5,%6,%7}, {%8,%9}, {%0,%1,%2,%3};"
        : "+f"(c[0]), "+f"(c[1]), "+f"(c[2]), "+f"(c[3])
        : "r"(a[0]), "r"(a[1]), "r"(a[2]), "r"(a[3]), "r"(b[0]), "r"(b[1]));
}

// ---------------------------------------------------------------------------
// Edge dtype detection: one warp, ballot over odd 32-bit words.
// int64 edge_index (values < 1e5) has all-zero high words.
// ---------------------------------------------------------------------------
__global__ void k_detect(const int* __restrict__ ei_raw) {
    int lane = threadIdx.x;                 // 0..31
    int v = ei_raw[1 + 2 * lane];           // odd words 1,3,...,63
    unsigned nz = __ballot_sync(0xFFFFFFFFu, v != 0);
    if (lane == 0) g_is64 = (nz == 0) ? 1 : 0;
}

__global__ void k_deg_init(int n) {
    int i = blockIdx.x * blockDim.x + threadIdx.x;
    if (i < n) g_deg[i] = 1.0f;  // self-loop
}

// Convert edge list to int32 + count in-degree (fused).
__global__ void k_convert(const void* __restrict__ ei, int e, int n) {
    int i = blockIdx.x * blockDim.x + threadIdx.x;
    if (i >= e) return;
    int s, d;
    if (g_is64) {
        const long long* p = (const long long*)ei;
        s = (int)p[i];
        d = (int)p[e + i];
    } else {
        const int* p = (const int*)ei;
        s = p[i];
        d = p[e + i];
    }
    g_src[i] = s;
    g_dst[i] = d;
    if ((unsigned)d < (unsigned)n) atomicAdd(&g_deg[d], 1.0f);
}

// ---------------------------------------------------------------------------
// One-time W split: W[k][n] fp32 -> bf16 hi/lo planes (row-major [k][n]).
// ---------------------------------------------------------------------------
__global__ void k_wsplit(const float* __restrict__ W) {
    int i = blockIdx.x * blockDim.x + threadIdx.x;   // < 16384
    float v = W[i];
    __nv_bfloat16 h = __float2bfloat16(v);
    __nv_bfloat16 l = __float2bfloat16(v - __bfloat162float(h));
    ((__nv_bfloat16*)g_Whi4)[i] = h;
    ((__nv_bfloat16*)g_Wlo4)[i] = l;
}

// ---------------------------------------------------------------------------
// HMMA GEMM: y = rsqrt(deg) * (x @ W) via bf16 hi/lo 3-term split.
// Per CTA: M=128 x N=128 x K=128, 8 warps, warp w -> rows 16w..16w+15.
// Also initializes out with y (self-loop contribution).
// ---------------------------------------------------------------------------
#define SM_A_HI 0
#define SM_A_LO (SM_A_HI + 128 * LDA * 2)   // 34816
#define SM_B_HI (SM_A_LO + 128 * LDA * 2)
#define SM_B_LO (SM_B_HI + 128 * LDA * 2)
#define SMEM_TOTAL (SM_B_LO + 128 * LDA * 2)  // 139264

__global__ void __launch_bounds__(GEMM_THREADS, 1)
k_gemm_mma(const float* __restrict__ x, float* __restrict__ out, int n) {
    extern __shared__ __align__(16) char smem[];
    const uint32_t smem_base = smem_u32(smem);
    const int tid  = threadIdx.x;
    const int w    = tid >> 5;
    const int lane = tid & 31;
    const int row0 = blockIdx.x * TILE_M;

    // --- Copy precomputed W planes into padded SMEM (uint4 = 8 bf16) ---
    #pragma unroll 4
    for (int i = tid; i < 2048; i += GEMM_THREADS) {
        int r  = i >> 4;            // k row (16 uint4 per 128-col row)
        int c8 = (i & 15) * 8;      // n col
        size_t o = (size_t)(r * LDA + c8) * 2;   // 16B-aligned (272r + 16c)
        *(uint4*)(smem + SM_B_HI + o) = g_Whi4[i];
        *(uint4*)(smem + SM_B_LO + o) = g_Wlo4[i];
    }

    // --- Convert x tile -> As_hi/As_lo (row-major [m][k], padded) ---
    #pragma unroll 4
    for (int i = tid; i < 128 * 32; i += GEMM_THREADS) {
        int r  = i >> 5;
        int c4 = (i & 31) * 4;
        int row = row0 + r;
        if (row >= n) row = n - 1;   // clamp; OOB rows never stored
        float4 v = *(const float4*)&x[(size_t)row * D + c4];
        __nv_bfloat16 hx = __float2bfloat16(v.x), hy = __float2bfloat16(v.y);
        __nv_bfloat16 hz = __float2bfloat16(v.z), hw = __float2bfloat16(v.w);
        __nv_bfloat16 lx = __float2bfloat16(v.x - __bfloat162float(hx));
        __nv_bfloat16 ly = __float2bfloat16(v.y - __bfloat162float(hy));
        __nv_bfloat16 lz = __float2bfloat16(v.z - __bfloat162float(hz));
        __nv_bfloat16 lw = __float2bfloat16(v.w - __bfloat162float(hw));
        size_t o = (size_t)(r * LDA + c4) * 2;
        *(__nv_bfloat162*)(smem + SM_A_HI + o)     = __nv_bfloat162(hx, hy);
        *(__nv_bfloat162*)(smem + SM_A_HI + o + 4) = __nv_bfloat162(hz, hw);
        *(__nv_bfloat162*)(smem + SM_A_LO + o)     = __nv_bfloat162(lx, ly);
        *(__nv_bfloat162*)(smem + SM_A_LO + o + 4) = __nv_bfloat162(lz, lw);
    }
    __syncthreads();

    // --- Mainloop: 8 k-steps (k16), 16 n-tiles (n8), 3 split terms each ---
    float acc[16][4];
    #pragma unroll
    for (int t = 0; t < 16; t++)
        acc[t][0] = acc[t][1] = acc[t][2] = acc[t][3] = 0.0f;

    const int m0 = w * 16;
    const int amat = lane >> 3;            // 0..3
    const int arow = m0 + ((amat & 1) * 8) + (lane & 7);
    const int acol8 = (amat >> 1) * 8;     // k-offset 0 or 8
    const int bmat = (lane >> 3) & 1;
    const int brow_base = bmat * 8 + (lane & 7);

    #pragma unroll
    for (int ks = 0; ks < 8; ks++) {
        uint32_t a_hi[4], a_lo[4];
        uint32_t a_addr = smem_base + SM_A_HI +
                          (uint32_t)(arow * LDA + ks * 16 + acol8) * 2;
        ldsm_x4(a_hi[0], a_hi[1], a_hi[2], a_hi[3], a_addr);
        ldsm_x4(a_lo[0], a_lo[1], a_lo[2], a_lo[3],
                a_addr + (SM_A_LO - SM_A_HI));

        uint32_t b_base = smem_base + SM_B_HI +
                          (uint32_t)((ks * 16 + brow_base) * LDA) * 2;
        #pragma unroll
        for (int nt = 0; nt < 16; nt++) {
            uint32_t b_hi[2], b_lo[2];
            uint32_t b_addr = b_base + nt * 16;   // n0 = nt*8, *2 bytes
            ldsm_x2_trans(b_hi[0], b_hi[1], b_addr);
            ldsm_x2_trans(b_lo[0], b_lo[1], b_addr + (SM_B_LO - SM_B_HI));
            mma_bf16(acc[nt], a_hi, b_hi);
            mma_bf16(acc[nt], a_hi, b_lo);
            mma_bf16(acc[nt], a_lo, b_hi);
        }
    }

    // --- Epilogue: scale by rsqrt(deg), write y and out (self-loop) ---
    const int r_lo  = lane >> 2;          // 0..7
    const int cpair = (lane & 3) * 2;
    const int row_a = row0 + m0 + r_lo;
    const int row_b = row_a + 8;
    const float sa = (row_a < n) ? rsqrtf(g_deg[row_a]) : 0.0f;
    const float sb = (row_b < n) ? rsqrtf(g_deg[row_b]) : 0.0f;

    #pragma unroll
    for (int nt = 0; nt < 16; nt++) {
        int col = nt * 8 + cpair;
        if (row_a < n) {
            float2 v = make_float2(acc[nt][0] * sa, acc[nt][1] * sa);
            *(float2*)&g_y[(size_t)row_a * D + col] = v;
            *(float2*)&out[(size_t)row_a * D + col] = v;
        }
        if (row_b < n) {
            float2 v = make_float2(acc[nt][2] * sb, acc[nt][3] * sb);
            *(float2*)&g_y[(size_t)row_b * D + col] = v;
            *(float2*)&out[(size_t)row_b * D + col] = v;
        }
    }
}

// ---------------------------------------------------------------------------
// Edge scatter: one warp per edge, lane handles 4 contiguous floats.
// out[dst, :] += y[src, :]   (vector red.global.add.v4.f32)
// ---------------------------------------------------------------------------
__device__ __forceinline__ void red_add_v4(float* addr, float4 v) {
    asm volatile("red.global.add.v4.f32 [%0], {%1, %2, %3, %4};"
                 :: "l"(addr), "f"(v.x), "f"(v.y), "f"(v.z), "f"(v.w)
                 : "memory");
}

__global__ void __launch_bounds__(256) k_scatter(float* __restrict__ out,
                                                 int e, int n) {
    int warp = blockIdx.x * (blockDim.x >> 5) + (threadIdx.x >> 5);
    if (warp >= e) return;
    int lane = threadIdx.x & 31;

    unsigned src = (unsigned)g_src[warp];
    unsigned dst = (unsigned)g_dst[warp];
    if (src >= (unsigned)n || dst >= (unsigned)n) return;

    float4 v = *(const float4*)&g_y[(size_t)src * D + lane * 4];
    red_add_v4(&out[(size_t)dst * D + lane * 4], v);
}

// ---------------------------------------------------------------------------
// Finalize: out[i,:] = rsqrt(deg[i]) * out[i,:] + b
// ---------------------------------------------------------------------------
__global__ void k_final(const float* __restrict__ b, float* __restrict__ out,
                        int n) {
    int i = blockIdx.x * blockDim.x + threadIdx.x;  // float4 index
    if (i < n * 32) {
        float s = rsqrtf(g_deg[i >> 5]);
        float4 v = ((const float4*)out)[i];
        float4 bb = ((const float4*)b)[i & 31];
        v.x = fmaf(v.x, s, bb.x);
        v.y = fmaf(v.y, s, bb.y);
        v.z = fmaf(v.z, s, bb.z);
        v.w = fmaf(v.w, s, bb.w);
        ((float4*)out)[i] = v;
    }
}

// ---------------------------------------------------------------------------
extern "C" void kernel_launch(void* const* d_in, const int* in_sizes, int n_in,
                              void* d_out, int out_size) {
    const float* x  = (const float*)d_in[0];
    const void*  ei = (const void*)d_in[1];
    const float* W  = (const float*)d_in[2];
    const float* b  = (const float*)d_in[3];
    float* out = (float*)d_out;

    int n = in_sizes[0] / D;   // 100000
    int e = in_sizes[1] / 2;   // 600000

    k_detect<<<1, 32>>>((const int*)ei);
    k_deg_init<<<(n + 255) / 256, 256>>>(n);
    k_convert<<<(e + 255) / 256, 256>>>(ei, e, n);
    k_wsplit<<<64, 256>>>(W);

    cudaFuncSetAttribute(k_gemm_mma, cudaFuncAttributeMaxDynamicSharedMemorySize,
                         SMEM_TOTAL);
    k_gemm_mma<<<(n + TILE_M - 1) / TILE_M, GEMM_THREADS, SMEM_TOTAL>>>(x, out, n);

    k_scatter<<<(e + 7) / 8, 256>>>(out, e, n);

    k_final<<<(n * 32 + 255) / 256, 256>>>(b, out, n);
}

// round 8
// speedup vs baseline: 1.6254x; 1.3024x over previous
#include <cuda_runtime.h>
#include <cuda_bf16.h>
#include <cstdint>

#define MAX_NODES 100000
#define MAX_EDGES 600000
#define D 128
#define TILE_M 128
#define GEMM_THREADS 256
#define LDA 136                    // padded row stride (elements) -> 272B, LDSM conflict-free

// ---------------------------------------------------------------------------
// Device scratch (no cudaMalloc allowed)
// ---------------------------------------------------------------------------
__device__ int   g_is64;
__device__ int   g_src[MAX_EDGES];
__device__ int   g_dst[MAX_EDGES];
__device__ int   g_esrc[MAX_EDGES];               // CSR col indices (src per dst)
__device__ int   g_cnt[MAX_NODES];                // in-degree (excl. self-loop)
__device__ int   g_off[MAX_NODES];                // CSR row offsets (exclusive scan)
__device__ int   g_cursor[MAX_NODES];             // fill cursors
__device__ int   g_bsum[512];                     // scan block sums
__device__ float g_y[(size_t)MAX_NODES * D];      // y = dinv[i] * (x[i] @ W)
__device__ uint4 g_Whi4[2048];                    // W hi plane, bf16 [k][n]
__device__ uint4 g_Wlo4[2048];                    // W lo plane, bf16 [k][n]

// ---------------------------------------------------------------------------
// PTX helpers: ldmatrix + bf16 mma.sync (plain sm_103-safe, no tcgen05)
// ---------------------------------------------------------------------------
__device__ __forceinline__ uint32_t smem_u32(const void* p) {
    uint32_t a;
    asm("{ .reg .u64 t; cvta.to.shared.u64 t, %1; cvt.u32.u64 %0, t; }"
        : "=r"(a) : "l"(p));
    return a;
}

__device__ __forceinline__ void ldsm_x4(uint32_t& r0, uint32_t& r1,
                                        uint32_t& r2, uint32_t& r3,
                                        uint32_t addr) {
    asm volatile("ldmatrix.sync.aligned.m8n8.x4.shared.b16 {%0,%1,%2,%3}, [%4];"
                 : "=r"(r0), "=r"(r1), "=r"(r2), "=r"(r3) : "r"(addr));
}

__device__ __forceinline__ void ldsm_x2_trans(uint32_t& r0, uint32_t& r1,
                                              uint32_t addr) {
    asm volatile("ldmatrix.sync.aligned.m8n8.x2.trans.shared.b16 {%0,%1}, [%2];"
                 : "=r"(r0), "=r"(r1) : "r"(addr));
}

__device__ __forceinline__ void mma_bf16(float* c, const uint32_t* a,
                                         const uint32_t* b) {
    asm volatile(
        "mma.sync.aligned.m16n8k16.row.col.f32.bf16.bf16.f32 "
        "{%0,%1,%2,%3}, {%4,%5,%6,%7}, {%8,%9}, {%0,%1,%2,%3};"
        : "+f"(c[0]), "+f"(c[1]), "+f"(c[2]), "+f"(c[3])
        : "r"(a[0]), "r"(a[1]), "r"(a[2]), "r"(a[3]), "r"(b[0]), "r"(b[1]));
}

// ---------------------------------------------------------------------------
// Edge dtype detection: one warp, ballot over odd 32-bit words.
// ---------------------------------------------------------------------------
__global__ void k_detect(const int* __restrict__ ei_raw) {
    int lane = threadIdx.x;
    int v = ei_raw[1 + 2 * lane];
    unsigned nz = __ballot_sync(0xFFFFFFFFu, v != 0);
    if (lane == 0) g_is64 = (nz == 0) ? 1 : 0;
}

__global__ void k_zero(int n) {
    int i = blockIdx.x * blockDim.x + threadIdx.x;
    if (i < n) g_cnt[i] = 0;
}

// Convert edge list to int32 + in-degree histogram (int atomics).
__global__ void k_convert(const void* __restrict__ ei, int e, int n) {
    int i = blockIdx.x * blockDim.x + threadIdx.x;
    if (i >= e) return;
    int s, d;
    if (g_is64) {
        const long long* p = (const long long*)ei;
        s = (int)p[i];
        d = (int)p[e + i];
    } else {
        const int* p = (const int*)ei;
        s = p[i];
        d = p[e + i];
    }
    g_src[i] = s;
    g_dst[i] = d;
    if ((unsigned)d < (unsigned)n) atomicAdd(&g_cnt[d], 1);
}

// ---------------------------------------------------------------------------
// Exclusive scan of g_cnt -> g_off (3 kernels), then cursor init.
// ---------------------------------------------------------------------------
__global__ void k_scan1(int n) {
    __shared__ int sh[256];
    int i = blockIdx.x * 256 + threadIdx.x;
    int v = (i < n) ? g_cnt[i] : 0;
    sh[threadIdx.x] = v;
    __syncthreads();
    #pragma unroll
    for (int off = 1; off < 256; off <<= 1) {
        int t = (threadIdx.x >= off) ? sh[threadIdx.x - off] : 0;
        __syncthreads();
        sh[threadIdx.x] += t;
        __syncthreads();
    }
    if (i < n) g_off[i] = sh[threadIdx.x] - v;   // exclusive within block
    if (threadIdx.x == 255) g_bsum[blockIdx.x] = sh[255];
}

__global__ void k_scan2(int nb) {
    __shared__ int sh[512];
    int v = (threadIdx.x < nb) ? g_bsum[threadIdx.x] : 0;
    sh[threadIdx.x] = v;
    __syncthreads();
    #pragma unroll
    for (int off = 1; off < 512; off <<= 1) {
        int t = (threadIdx.x >= off) ? sh[threadIdx.x - off] : 0;
        __syncthreads();
        sh[threadIdx.x] += t;
        __syncthreads();
    }
    if (threadIdx.x < nb) g_bsum[threadIdx.x] = sh[threadIdx.x] - v;
}

__global__ void k_scan3(int n) {
    int i = blockIdx.x * 256 + threadIdx.x;
    if (i < n) {
        int o = g_off[i] + g_bsum[i >> 8];
        g_off[i] = o;
        g_cursor[i] = o;
    }
}

// Fill CSR: g_esrc[pos] = src, grouped by dst.
__global__ void k_fill(int e, int n) {
    int i = blockIdx.x * blockDim.x + threadIdx.x;
    if (i >= e) return;
    int d = g_dst[i];
    if ((unsigned)d >= (unsigned)n) return;
    int s = g_src[i];
    if ((unsigned)s >= (unsigned)n) s = 0;
    int pos = atomicAdd(&g_cursor[d], 1);
    g_esrc[pos] = s;
}

// ---------------------------------------------------------------------------
// One-time W split: W[k][n] fp32 -> bf16 hi/lo planes (row-major [k][n]).
// ---------------------------------------------------------------------------
__global__ void k_wsplit(const float* __restrict__ W) {
    int i = blockIdx.x * blockDim.x + threadIdx.x;   // < 16384
    float v = W[i];
    __nv_bfloat16 h = __float2bfloat16(v);
    __nv_bfloat16 l = __float2bfloat16(v - __bfloat162float(h));
    ((__nv_bfloat16*)g_Whi4)[i] = h;
    ((__nv_bfloat16*)g_Wlo4)[i] = l;
}

// ---------------------------------------------------------------------------
// HMMA GEMM: y = rsqrt(deg) * (x @ W) via bf16 hi/lo 3-term split.
// Writes ONLY g_y (out is produced by the gather kernel).
// ---------------------------------------------------------------------------
#define SM_A_HI 0
#define SM_A_LO (SM_A_HI + 128 * LDA * 2)   // 34816
#define SM_B_HI (SM_A_LO + 128 * LDA * 2)
#define SM_B_LO (SM_B_HI + 128 * LDA * 2)
#define SMEM_TOTAL (SM_B_LO + 128 * LDA * 2)  // 139264

__global__ void __launch_bounds__(GEMM_THREADS, 1)
k_gemm_mma(const float* __restrict__ x, int n) {
    extern __shared__ __align__(16) char smem[];
    const uint32_t smem_base = smem_u32(smem);
    const int tid  = threadIdx.x;
    const int w    = tid >> 5;
    const int lane = tid & 31;
    const int row0 = blockIdx.x * TILE_M;

    // --- Copy precomputed W planes into padded SMEM (uint4 = 8 bf16) ---
    #pragma unroll 4
    for (int i = tid; i < 2048; i += GEMM_THREADS) {
        int r  = i >> 4;
        int c8 = (i & 15) * 8;
        size_t o = (size_t)(r * LDA + c8) * 2;
        *(uint4*)(smem + SM_B_HI + o) = g_Whi4[i];
        *(uint4*)(smem + SM_B_LO + o) = g_Wlo4[i];
    }

    // --- Convert x tile -> As_hi/As_lo (row-major [m][k], padded) ---
    #pragma unroll 4
    for (int i = tid; i < 128 * 32; i += GEMM_THREADS) {
        int r  = i >> 5;
        int c4 = (i & 31) * 4;
        int row = row0 + r;
        if (row >= n) row = n - 1;
        float4 v = *(const float4*)&x[(size_t)row * D + c4];
        __nv_bfloat16 hx = __float2bfloat16(v.x), hy = __float2bfloat16(v.y);
        __nv_bfloat16 hz = __float2bfloat16(v.z), hw = __float2bfloat16(v.w);
        __nv_bfloat16 lx = __float2bfloat16(v.x - __bfloat162float(hx));
        __nv_bfloat16 ly = __float2bfloat16(v.y - __bfloat162float(hy));
        __nv_bfloat16 lz = __float2bfloat16(v.z - __bfloat162float(hz));
        __nv_bfloat16 lw = __float2bfloat16(v.w - __bfloat162float(hw));
        size_t o = (size_t)(r * LDA + c4) * 2;
        *(__nv_bfloat162*)(smem + SM_A_HI + o)     = __nv_bfloat162(hx, hy);
        *(__nv_bfloat162*)(smem + SM_A_HI + o + 4) = __nv_bfloat162(hz, hw);
        *(__nv_bfloat162*)(smem + SM_A_LO + o)     = __nv_bfloat162(lx, ly);
        *(__nv_bfloat162*)(smem + SM_A_LO + o + 4) = __nv_bfloat162(lz, lw);
    }
    __syncthreads();

    float acc[16][4];
    #pragma unroll
    for (int t = 0; t < 16; t++)
        acc[t][0] = acc[t][1] = acc[t][2] = acc[t][3] = 0.0f;

    const int m0 = w * 16;
    const int amat = lane >> 3;
    const int arow = m0 + ((amat & 1) * 8) + (lane & 7);
    const int acol8 = (amat >> 1) * 8;
    const int bmat = (lane >> 3) & 1;
    const int brow_base = bmat * 8 + (lane & 7);

    #pragma unroll
    for (int ks = 0; ks < 8; ks++) {
        uint32_t a_hi[4], a_lo[4];
        uint32_t a_addr = smem_base + SM_A_HI +
                          (uint32_t)(arow * LDA + ks * 16 + acol8) * 2;
        ldsm_x4(a_hi[0], a_hi[1], a_hi[2], a_hi[3], a_addr);
        ldsm_x4(a_lo[0], a_lo[1], a_lo[2], a_lo[3],
                a_addr + (SM_A_LO - SM_A_HI));

        uint32_t b_base = smem_base + SM_B_HI +
                          (uint32_t)((ks * 16 + brow_base) * LDA) * 2;
        #pragma unroll
        for (int nt = 0; nt < 16; nt++) {
            uint32_t b_hi[2], b_lo[2];
            uint32_t b_addr = b_base + nt * 16;
            ldsm_x2_trans(b_hi[0], b_hi[1], b_addr);
            ldsm_x2_trans(b_lo[0], b_lo[1], b_addr + (SM_B_LO - SM_B_HI));
            mma_bf16(acc[nt], a_hi, b_hi);
            mma_bf16(acc[nt], a_hi, b_lo);
            mma_bf16(acc[nt], a_lo, b_hi);
        }
    }

    // --- Epilogue: scale by rsqrt(deg), write y only ---
    const int r_lo  = lane >> 2;
    const int cpair = (lane & 3) * 2;
    const int row_a = row0 + m0 + r_lo;
    const int row_b = row_a + 8;
    const float sa = (row_a < n) ? rsqrtf((float)g_cnt[row_a] + 1.0f) : 0.0f;
    const float sb = (row_b < n) ? rsqrtf((float)g_cnt[row_b] + 1.0f) : 0.0f;

    #pragma unroll
    for (int nt = 0; nt < 16; nt++) {
        int col = nt * 8 + cpair;
        if (row_a < n) {
            float2 v = make_float2(acc[nt][0] * sa, acc[nt][1] * sa);
            *(float2*)&g_y[(size_t)row_a * D + col] = v;
        }
        if (row_b < n) {
            float2 v = make_float2(acc[nt][2] * sb, acc[nt][3] * sb);
            *(float2*)&g_y[(size_t)row_b * D + col] = v;
        }
    }
}

// ---------------------------------------------------------------------------
// Gather: one warp per destination node. Lanes batch-load up to 32 src ids
// (coalesced), shfl-broadcast them, accumulate float4 columns in registers.
// out[d] = rsqrt(deg) * (y[d] + sum y[src]) + b  — no atomics, final fused.
// ---------------------------------------------------------------------------
__global__ void __launch_bounds__(256) k_gather(const float* __restrict__ b,
                                                float* __restrict__ out,
                                                int n) {
    int d = (blockIdx.x * 256 + threadIdx.x) >> 5;
    if (d >= n) return;
    int lane = threadIdx.x & 31;

    int beg = g_off[d];
    int cnt = g_cnt[d];

    float4 acc = *(const float4*)&g_y[(size_t)d * D + lane * 4];  // self-loop

    int k = 0;
    while (k < cnt) {
        int m = cnt - k;
        if (m > 32) m = 32;
        int s = (lane < m) ? g_esrc[beg + k + lane] : 0;
        for (int j = 0; j < m; j++) {
            int sj = __shfl_sync(0xFFFFFFFFu, s, j);
            float4 v = *(const float4*)&g_y[(size_t)sj * D + lane * 4];
            acc.x += v.x; acc.y += v.y; acc.z += v.z; acc.w += v.w;
        }
        k += m;
    }

    float sc = rsqrtf((float)cnt + 1.0f);
    float4 bb = *(const float4*)&b[lane * 4];
    float4 r;
    r.x = fmaf(acc.x, sc, bb.x);
    r.y = fmaf(acc.y, sc, bb.y);
    r.z = fmaf(acc.z, sc, bb.z);
    r.w = fmaf(acc.w, sc, bb.w);
    *(float4*)&out[(size_t)d * D + lane * 4] = r;
}

// ---------------------------------------------------------------------------
extern "C" void kernel_launch(void* const* d_in, const int* in_sizes, int n_in,
                              void* d_out, int out_size) {
    const float* x  = (const float*)d_in[0];
    const void*  ei = (const void*)d_in[1];
    const float* W  = (const float*)d_in[2];
    const float* b  = (const float*)d_in[3];
    float* out = (float*)d_out;

    int n = in_sizes[0] / D;   // 100000
    int e = in_sizes[1] / 2;   // 600000
    int nb = (n + 255) / 256;  // scan blocks (391)

    k_detect<<<1, 32>>>((const int*)ei);
    k_zero<<<nb, 256>>>(n);
    k_convert<<<(e + 255) / 256, 256>>>(ei, e, n);

    k_scan1<<<nb, 256>>>(n);
    k_scan2<<<1, 512>>>(nb);
    k_scan3<<<nb, 256>>>(n);
    k_fill<<<(e + 255) / 256, 256>>>(e, n);

    k_wsplit<<<64, 256>>>(W);

    cudaFuncSetAttribute(k_gemm_mma, cudaFuncAttributeMaxDynamicSharedMemorySize,
                         SMEM_TOTAL);
    k_gemm_mma<<<(n + TILE_M - 1) / TILE_M, GEMM_THREADS, SMEM_TOTAL>>>(x, n);

    k_gather<<<(n * 32 + 255) / 256, 256>>>(b, out, n);
}